// round 1
// baseline (speedup 1.0000x reference)
#include <cuda_runtime.h>
#include <math_constants.h>
#include <cstdint>

#define BB 16
#define WW 2048
#define CC 512
#define NN (BB*WW*CC)

// ---------- scratch (no allocations allowed) ----------
__device__ float g_Xs[NN];           // X_spatial [B,W,C]  (64 MB)
__device__ float g_tt[BB*WW];        // temporal token mean [B,W]
__device__ float g_invdeg[BB*CC];    // 1/in_deg [B,C]
__device__ float g_degpart[BB*8*CC]; // partial column sums

__device__ __forceinline__ float softplusf(float x) {
    return fmaxf(x, 0.f) + log1pf(expf(-fabsf(x)));
}

// ---------- K1a: partial column sums of relu(adj) ----------
__global__ void deg_partial_kernel(const float* __restrict__ adj) {
    int b = blockIdx.y, chunk = blockIdx.x;
    int i0 = chunk * 64;
    const float* A = adj + (size_t)b * CC * CC;
    for (int j = threadIdx.x; j < CC; j += blockDim.x) {
        float s = 0.f;
        #pragma unroll 8
        for (int i = 0; i < 64; i++)
            s += fmaxf(A[(size_t)(i0 + i) * CC + j], 0.f);
        g_degpart[(b * 8 + chunk) * CC + j] = s;
    }
}

// ---------- K1b: reduce + invert ----------
__global__ void invdeg_kernel() {
    int idx = blockIdx.x * blockDim.x + threadIdx.x;
    if (idx >= BB * CC) return;
    int b = idx / CC, j = idx % CC;
    float s = 0.f;
    #pragma unroll
    for (int c = 0; c < 8; c++) s += g_degpart[(b * 8 + c) * CC + j];
    g_invdeg[idx] = 1.0f / fmaxf(s, 1e-4f);
}

// ---------- K2: SGEMM  Xs[b] = X[b] @ relu(adj[b]) * invdeg_col ----------
#define BM 128
#define BN 128
#define BK 8

__global__ __launch_bounds__(256, 2)
void gemm_kernel(const float* __restrict__ X, const float* __restrict__ adj) {
    __shared__ float As[BK][BM + 4];
    __shared__ float Bs[BK][BN];
    int b = blockIdx.z;
    const float* Ap = X + (size_t)b * WW * CC + (size_t)blockIdx.y * BM * CC;
    const float* Bp = adj + (size_t)b * CC * CC + blockIdx.x * BN;
    int tid = threadIdx.x;
    int tx = tid & 15, ty = tid >> 4;
    int arow = tid >> 1, acol = (tid & 1) * 4;
    int brow = tid >> 5, bcol = (tid & 31) * 4;

    float acc[8][8];
    #pragma unroll
    for (int m = 0; m < 8; m++)
        #pragma unroll
        for (int n = 0; n < 8; n++) acc[m][n] = 0.f;

    for (int k0 = 0; k0 < CC; k0 += BK) {
        float4 av = *(const float4*)(Ap + (size_t)arow * CC + k0 + acol);
        float4 bv = *(const float4*)(Bp + (size_t)(k0 + brow) * CC + bcol);
        As[acol + 0][arow] = av.x;
        As[acol + 1][arow] = av.y;
        As[acol + 2][arow] = av.z;
        As[acol + 3][arow] = av.w;
        bv.x = fmaxf(bv.x, 0.f); bv.y = fmaxf(bv.y, 0.f);
        bv.z = fmaxf(bv.z, 0.f); bv.w = fmaxf(bv.w, 0.f);
        *(float4*)&Bs[brow][bcol] = bv;
        __syncthreads();
        #pragma unroll
        for (int kk = 0; kk < BK; kk++) {
            float a[8], bb[8];
            *(float4*)&a[0]  = *(const float4*)&As[kk][ty * 8];
            *(float4*)&a[4]  = *(const float4*)&As[kk][ty * 8 + 4];
            *(float4*)&bb[0] = *(const float4*)&Bs[kk][tx * 8];
            *(float4*)&bb[4] = *(const float4*)&Bs[kk][tx * 8 + 4];
            #pragma unroll
            for (int m = 0; m < 8; m++)
                #pragma unroll
                for (int n = 0; n < 8; n++)
                    acc[m][n] = fmaf(a[m], bb[n], acc[m][n]);
        }
        __syncthreads();
    }

    int gcol = blockIdx.x * BN + tx * 8;
    float sc[8];
    #pragma unroll
    for (int n = 0; n < 8; n++) sc[n] = g_invdeg[b * CC + gcol + n];
    float* out = g_Xs + (size_t)b * WW * CC + (size_t)blockIdx.y * BM * CC;
    #pragma unroll
    for (int m = 0; m < 8; m++) {
        int row = ty * 8 + m;
        float4 v0 = make_float4(acc[m][0]*sc[0], acc[m][1]*sc[1], acc[m][2]*sc[2], acc[m][3]*sc[3]);
        float4 v1 = make_float4(acc[m][4]*sc[4], acc[m][5]*sc[5], acc[m][6]*sc[6], acc[m][7]*sc[7]);
        *(float4*)(out + (size_t)row * CC + gcol)     = v0;
        *(float4*)(out + (size_t)row * CC + gcol + 4) = v1;
    }
}

// ---------- K3: temporal token = row mean over C ----------
__global__ void token_kernel() {
    int gwarp = (blockIdx.x * blockDim.x + threadIdx.x) >> 5;
    int lane = threadIdx.x & 31;
    if (gwarp >= BB * WW) return;
    const float4* row = (const float4*)(g_Xs + (size_t)gwarp * CC);
    float s = 0.f;
    #pragma unroll
    for (int q = 0; q < 4; q++) {
        float4 v = row[lane + 32 * q];
        s += v.x + v.y + v.z + v.w;
    }
    #pragma unroll
    for (int o = 16; o; o >>= 1) s += __shfl_xor_sync(0xffffffffu, s, o);
    if (lane == 0) g_tt[gwarp] = s * (1.0f / CC);
}

// ---------- K4: fused band-attention + epilogue ----------
#define TI 32
#define CJ 64
#define K2CAP 40
#define XR (TI + 2 * K2CAP)     // 112
#define NDTMAX (2 * K2CAP + 1)  // 81

__global__ __launch_bounds__(128)
void epilogue_kernel(const float* __restrict__ lt,
                     const float* __restrict__ wq, const float* __restrict__ bq,
                     const float* __restrict__ wk, const float* __restrict__ bk,
                     const float* __restrict__ wv, const float* __restrict__ bv,
                     const float* __restrict__ wmu, const float* __restrict__ bmu,
                     const float* __restrict__ wsig, const float* __restrict__ bsig,
                     const int* __restrict__ k1p, const int* __restrict__ k2p,
                     float* __restrict__ out) {
    __shared__ float sX[XR][CJ];
    __shared__ float sW[TI][NDTMAX];
    __shared__ float sTT[XR];
    __shared__ float sSac[TI];

    int b = blockIdx.z, i0 = blockIdx.y * TI, c0 = blockIdx.x * CJ;
    int k1 = k1p[0], k2 = k2p[0];
    float invt = 1.0f / (softplusf(lt[0]) + 1e-4f);
    float vwq = wq[0], vbq = bq[0], vwk = wk[0], vbk = bk[0];
    float vwv = wv[0], vbv = bv[0];
    float vwmu = wmu[0], vbmu = bmu[0], vws = wsig[0], vbs = bsig[0];
    int tid = threadIdx.x;
    float* muo = out;
    float* sgo = out + (size_t)NN;
    float* sco = out + 2 * (size_t)NN;

    if (k2 <= K2CAP) {
        int jlo = i0 - k2;
        int nrows = TI + 2 * k2;
        int ndt = 2 * k2 + 1;
        // load X_spatial window + token window
        for (int idx = tid; idx < nrows * (CJ / 4); idx += 128) {
            int row = idx >> 4;
            int c4 = (idx & 15) * 4;
            int j = jlo + row;
            float4 v = make_float4(0.f, 0.f, 0.f, 0.f);
            if (j >= 0 && j < WW)
                v = *(const float4*)(g_Xs + (size_t)(b * WW + j) * CC + c0 + c4);
            *(float4*)&sX[row][c4] = v;
        }
        for (int idx = tid; idx < nrows; idx += 128) {
            int j = jlo + idx;
            sTT[idx] = (j >= 0 && j < WW) ? g_tt[b * WW + j] : 0.f;
        }
        __syncthreads();

        // per-row attention weights (one warp per row, round-robin)
        int lane = tid & 31, wid = tid >> 5;
        for (int r = wid; r < TI; r += 4) {
            int i = i0 + r;
            float qi = fmaf(vwq, sTT[r + k2], vbq);
            float m = -CUDART_INF_F;
            for (int p = lane; p < ndt; p += 32) {
                int dt = p - k2;
                int j = i + dt;
                bool valid = (abs(dt) >= k1) && (j >= 0) && (j < WW);
                float l = valid ? qi * fmaf(vwk, sTT[r + p], vbk) * invt : -CUDART_INF_F;
                sW[r][p] = l;
                m = fmaxf(m, l);
            }
            #pragma unroll
            for (int o = 16; o; o >>= 1) m = fmaxf(m, __shfl_xor_sync(0xffffffffu, m, o));
            if (m == -CUDART_INF_F) {
                // empty band -> identity row
                for (int p = lane; p < ndt; p += 32) sW[r][p] = 0.f;
                __syncwarp();
                if (lane == 0) {
                    sW[r][k2] = 1.0f / (1.f + 1e-6f);
                    sSac[r] = 1.0f / (1.f + 1e-6f);
                }
            } else {
                float zs = 0.f;
                for (int p = lane; p < ndt; p += 32) {
                    float e = expf(sW[r][p] - m);   // exp(-inf)=0 for invalid
                    sW[r][p] = e;
                    zs += e;
                }
                #pragma unroll
                for (int o = 16; o; o >>= 1) zs += __shfl_xor_sync(0xffffffffu, zs, o);
                float invz = 1.0f / zs;
                float s2 = 0.f;
                for (int p = lane; p < ndt; p += 32) {
                    float en = sW[r][p] * invz;
                    sW[r][p] = en;
                    s2 += en;
                }
                #pragma unroll
                for (int o = 16; o; o >>= 1) s2 += __shfl_xor_sync(0xffffffffu, s2, o);
                float invd = 1.0f / (s2 + 1e-6f);
                for (int p = lane; p < ndt; p += 32) sW[r][p] *= invd;
                if (lane == 0) sSac[r] = s2 * invd;
            }
        }
        __syncthreads();

        // banded weighted sum + fused output
        int tx = tid & 15, ty = tid >> 4;
        int col = tx * 4;
        #pragma unroll
        for (int rr = 0; rr < 4; rr++) {
            int r = ty * 4 + rr;
            int i = i0 + r;
            float4 a = make_float4(0.f, 0.f, 0.f, 0.f);
            for (int p = 0; p < ndt; p++) {
                float w = sW[r][p];
                float4 x = *(const float4*)&sX[r + p][col];
                a.x = fmaf(w, x.x, a.x);
                a.y = fmaf(w, x.y, a.y);
                a.z = fmaf(w, x.z, a.z);
                a.w = fmaf(w, x.w, a.w);
            }
            float sac = sSac[r];
            float4 xo = *(const float4*)&sX[r + k2][col];
            float4 xf, mu, sg;
            xf.x = fmaf(vwv, a.x, vbv * sac) + xo.x;
            xf.y = fmaf(vwv, a.y, vbv * sac) + xo.y;
            xf.z = fmaf(vwv, a.z, vbv * sac) + xo.z;
            xf.w = fmaf(vwv, a.w, vbv * sac) + xo.w;
            mu.x = fminf(fmaxf(fmaf(vwmu, xf.x, vbmu), -20.f), 20.f);
            mu.y = fminf(fmaxf(fmaf(vwmu, xf.y, vbmu), -20.f), 20.f);
            mu.z = fminf(fmaxf(fmaf(vwmu, xf.z, vbmu), -20.f), 20.f);
            mu.w = fminf(fmaxf(fmaf(vwmu, xf.w, vbmu), -20.f), 20.f);
            sg.x = softplusf(fmaf(vws, xf.x, vbs)) + 0.1f;
            sg.y = softplusf(fmaf(vws, xf.y, vbs)) + 0.1f;
            sg.z = softplusf(fmaf(vws, xf.z, vbs)) + 0.1f;
            sg.w = softplusf(fmaf(vws, xf.w, vbs)) + 0.1f;
            size_t o = (size_t)(b * WW + i) * CC + c0 + col;
            *(float4*)(muo + o) = mu;
            *(float4*)(sgo + o) = sg;
            *(float4*)(sco + o) = make_float4(sac, sac, sac, sac);
        }
    } else {
        // correct slow fallback for k2 > K2CAP (reads through L2)
        int tx = tid & 15, ty = tid >> 4;
        int col = c0 + tx * 4;
        for (int rr = 0; rr < 4; rr++) {
            int r = ty * 4 + rr;
            int i = i0 + r;
            float qi = fmaf(vwq, g_tt[b * WW + i], vbq);
            float m = -CUDART_INF_F;
            for (int dt = -k2; dt <= k2; dt++) {
                int j = i + dt;
                if (abs(dt) < k1 || j < 0 || j >= WW) continue;
                float l = qi * fmaf(vwk, g_tt[b * WW + j], vbk) * invt;
                m = fmaxf(m, l);
            }
            float4 a = make_float4(0.f, 0.f, 0.f, 0.f);
            float sac = 1.0f / (1.f + 1e-6f);
            if (m == -CUDART_INF_F) {
                float w = sac;
                float4 xi = *(const float4*)(g_Xs + (size_t)(b * WW + i) * CC + col);
                a.x = w * xi.x; a.y = w * xi.y; a.z = w * xi.z; a.w = w * xi.w;
            } else {
                float Z = 0.f;
                for (int dt = -k2; dt <= k2; dt++) {
                    int j = i + dt;
                    if (abs(dt) < k1 || j < 0 || j >= WW) continue;
                    float l = qi * fmaf(vwk, g_tt[b * WW + j], vbk) * invt;
                    float e = expf(l - m);
                    Z += e;
                    float4 x = *(const float4*)(g_Xs + (size_t)(b * WW + j) * CC + col);
                    a.x = fmaf(e, x.x, a.x);
                    a.y = fmaf(e, x.y, a.y);
                    a.z = fmaf(e, x.z, a.z);
                    a.w = fmaf(e, x.w, a.w);
                }
                float s = 1.0f / (Z * (1.f + 1e-6f));
                a.x *= s; a.y *= s; a.z *= s; a.w *= s;
            }
            float4 xo = *(const float4*)(g_Xs + (size_t)(b * WW + i) * CC + col);
            float4 xf, mu, sg;
            xf.x = fmaf(vwv, a.x, vbv * sac) + xo.x;
            xf.y = fmaf(vwv, a.y, vbv * sac) + xo.y;
            xf.z = fmaf(vwv, a.z, vbv * sac) + xo.z;
            xf.w = fmaf(vwv, a.w, vbv * sac) + xo.w;
            mu.x = fminf(fmaxf(fmaf(vwmu, xf.x, vbmu), -20.f), 20.f);
            mu.y = fminf(fmaxf(fmaf(vwmu, xf.y, vbmu), -20.f), 20.f);
            mu.z = fminf(fmaxf(fmaf(vwmu, xf.z, vbmu), -20.f), 20.f);
            mu.w = fminf(fmaxf(fmaf(vwmu, xf.w, vbmu), -20.f), 20.f);
            sg.x = softplusf(fmaf(vws, xf.x, vbs)) + 0.1f;
            sg.y = softplusf(fmaf(vws, xf.y, vbs)) + 0.1f;
            sg.z = softplusf(fmaf(vws, xf.z, vbs)) + 0.1f;
            sg.w = softplusf(fmaf(vws, xf.w, vbs)) + 0.1f;
            size_t o = (size_t)(b * WW + i) * CC + col;
            *(float4*)(muo + o) = mu;
            *(float4*)(sgo + o) = sg;
            *(float4*)(sco + o) = make_float4(sac, sac, sac, sac);
        }
    }
}

// ---------- launch ----------
extern "C" void kernel_launch(void* const* d_in, const int* in_sizes, int n_in,
                              void* d_out, int out_size) {
    const float* X    = (const float*)d_in[0];
    const float* adj  = (const float*)d_in[1];
    const float* lt   = (const float*)d_in[2];
    const float* wq   = (const float*)d_in[3];
    const float* bq   = (const float*)d_in[4];
    const float* wk   = (const float*)d_in[5];
    const float* bk   = (const float*)d_in[6];
    const float* wv   = (const float*)d_in[7];
    const float* bv   = (const float*)d_in[8];
    const float* wmu  = (const float*)d_in[9];
    const float* bmu  = (const float*)d_in[10];
    const float* wsig = (const float*)d_in[11];
    const float* bsig = (const float*)d_in[12];
    const int*   k1p  = (const int*)d_in[13];
    const int*   k2p  = (const int*)d_in[14];
    float* out = (float*)d_out;

    dim3 g1(8, BB);
    deg_partial_kernel<<<g1, 256>>>(adj);
    invdeg_kernel<<<(BB * CC + 255) / 256, 256>>>();
    dim3 g2(CC / BN, WW / BM, BB);
    gemm_kernel<<<g2, 256>>>(X, adj);
    token_kernel<<<(BB * WW) / 8, 256>>>();
    dim3 g5(CC / CJ, WW / TI, BB);
    epilogue_kernel<<<g5, 128>>>(lt, wq, bq, wk, bk, wv, bv, wmu, bmu, wsig, bsig,
                                 k1p, k2p, out);
}

// round 2
// speedup vs baseline: 1.6562x; 1.6562x over previous
#include <cuda_runtime.h>
#include <math_constants.h>
#include <cstdint>

#define BB 16
#define WW 2048
#define CC 512
#define NN (BB*WW*CC)

// ---------- scratch (no allocations allowed) ----------
__device__ float g_Xs[NN];           // X_spatial [B,W,C]  (64 MB)
__device__ float g_tt[BB*WW];        // temporal token mean [B,W]
__device__ float g_invdeg[BB*CC];    // 1/in_deg [B,C]
__device__ float g_degpart[BB*8*CC]; // partial column sums

__device__ __forceinline__ float softplusf(float x) {
    return fmaxf(x, 0.f) + log1pf(expf(-fabsf(x)));
}

__device__ __forceinline__ uint32_t f2tf32(float x) {
    uint32_t r;
    asm("cvt.rna.tf32.f32 %0, %1;" : "=r"(r) : "f"(x));
    return r;
}

// split x into tf32 hi + tf32 lo  (3xTF32 trick: fp32-level accuracy)
__device__ __forceinline__ uint2 tf32_split(float x) {
    uint32_t hi = f2tf32(x);
    float rem = x - __uint_as_float(hi);
    uint32_t lo = f2tf32(rem);
    return make_uint2(hi, lo);
}

__device__ __forceinline__ void mma_tf32(float* c,
                                         uint32_t a0, uint32_t a1, uint32_t a2, uint32_t a3,
                                         uint32_t b0, uint32_t b1) {
    asm volatile(
        "mma.sync.aligned.m16n8k8.row.col.f32.tf32.tf32.f32 "
        "{%0,%1,%2,%3},{%4,%5,%6,%7},{%8,%9},{%0,%1,%2,%3};\n"
        : "+f"(c[0]), "+f"(c[1]), "+f"(c[2]), "+f"(c[3])
        : "r"(a0), "r"(a1), "r"(a2), "r"(a3), "r"(b0), "r"(b1));
}

// ---------- K1a: partial column sums of relu(adj) ----------
__global__ void deg_partial_kernel(const float* __restrict__ adj) {
    int b = blockIdx.y, chunk = blockIdx.x;
    int i0 = chunk * 64;
    const float* A = adj + (size_t)b * CC * CC;
    for (int j = threadIdx.x; j < CC; j += blockDim.x) {
        float s = 0.f;
        #pragma unroll 8
        for (int i = 0; i < 64; i++)
            s += fmaxf(A[(size_t)(i0 + i) * CC + j], 0.f);
        g_degpart[(b * 8 + chunk) * CC + j] = s;
    }
}

// ---------- K1b: reduce + invert ----------
__global__ void invdeg_kernel() {
    int idx = blockIdx.x * blockDim.x + threadIdx.x;
    if (idx >= BB * CC) return;
    int b = idx / CC, j = idx % CC;
    float s = 0.f;
    #pragma unroll
    for (int c = 0; c < 8; c++) s += g_degpart[(b * 8 + c) * CC + j];
    g_invdeg[idx] = 1.0f / fmaxf(s, 1e-4f);
}

// ---------- K2: 3xTF32 tensor-core SGEMM ----------
// Xs[b] = X[b] @ relu(adj[b]) * invdeg_col
#define BM 128
#define BN 128
#define BK 16
#define ASTRIDE 20    // uint2 stride: conflict-free LDS.64 fragment reads
#define BSTRIDE 132   // uint2 stride: conflict-free LDS.64 fragment reads

__global__ __launch_bounds__(256, 2)
void gemm_kernel(const float* __restrict__ X, const float* __restrict__ adj) {
    __shared__ uint2 As[BM][ASTRIDE];   // [m][k] as (hi,lo)
    __shared__ uint2 Bs[BK][BSTRIDE];   // [k][n] as (hi,lo)

    int b = blockIdx.z;
    const float* Ap = X + (size_t)b * WW * CC + (size_t)blockIdx.y * BM * CC;
    const float* Bp = adj + (size_t)b * CC * CC + blockIdx.x * BN;

    int tid = threadIdx.x;
    int lane = tid & 31, wid = tid >> 5;
    int quad = lane >> 2, tq = lane & 3;
    int wm = wid >> 1, wn = wid & 1;     // warp tile: rows [wm*32,+32), cols [wn*64,+64)

    // global load indices
    int a_row = tid >> 1;                // 0..127
    int a_kq  = (tid & 1) * 8;           // 0 or 8
    int b_k   = tid >> 4;                // 0..15
    int b_n4  = (tid & 15) * 8;          // 0..120

    float acc[2][8][4];
    #pragma unroll
    for (int am = 0; am < 2; am++)
        #pragma unroll
        for (int an = 0; an < 8; an++)
            #pragma unroll
            for (int q = 0; q < 4; q++) acc[am][an][q] = 0.f;

    for (int k0 = 0; k0 < CC; k0 += BK) {
        // --- load A tile: 2 float4 per thread ---
        #pragma unroll
        for (int h = 0; h < 2; h++) {
            float4 v = *(const float4*)(Ap + (size_t)a_row * CC + k0 + a_kq + h * 4);
            As[a_row][a_kq + h * 4 + 0] = tf32_split(v.x);
            As[a_row][a_kq + h * 4 + 1] = tf32_split(v.y);
            As[a_row][a_kq + h * 4 + 2] = tf32_split(v.z);
            As[a_row][a_kq + h * 4 + 3] = tf32_split(v.w);
        }
        // --- load B tile (relu on load): 2 float4 per thread ---
        #pragma unroll
        for (int h = 0; h < 2; h++) {
            float4 v = *(const float4*)(Bp + (size_t)(k0 + b_k) * CC + b_n4 + h * 4);
            Bs[b_k][b_n4 + h * 4 + 0] = tf32_split(fmaxf(v.x, 0.f));
            Bs[b_k][b_n4 + h * 4 + 1] = tf32_split(fmaxf(v.y, 0.f));
            Bs[b_k][b_n4 + h * 4 + 2] = tf32_split(fmaxf(v.z, 0.f));
            Bs[b_k][b_n4 + h * 4 + 3] = tf32_split(fmaxf(v.w, 0.f));
        }
        __syncthreads();

        #pragma unroll
        for (int ks = 0; ks < 2; ks++) {
            int kb = ks * 8;
            uint2 ah[2][4];
            #pragma unroll
            for (int am = 0; am < 2; am++) {
                int r0 = wm * 32 + am * 16 + quad;
                ah[am][0] = As[r0][kb + tq];
                ah[am][1] = As[r0 + 8][kb + tq];
                ah[am][2] = As[r0][kb + 4 + tq];
                ah[am][3] = As[r0 + 8][kb + 4 + tq];
            }
            #pragma unroll
            for (int an = 0; an < 8; an++) {
                int c0 = wn * 64 + an * 8 + quad;
                uint2 b0 = Bs[kb + tq][c0];
                uint2 b1 = Bs[kb + 4 + tq][c0];
                #pragma unroll
                for (int am = 0; am < 2; am++) {
                    float* c = acc[am][an];
                    // hi*hi + hi*lo + lo*hi
                    mma_tf32(c, ah[am][0].x, ah[am][1].x, ah[am][2].x, ah[am][3].x, b0.x, b1.x);
                    mma_tf32(c, ah[am][0].x, ah[am][1].x, ah[am][2].x, ah[am][3].x, b0.y, b1.y);
                    mma_tf32(c, ah[am][0].y, ah[am][1].y, ah[am][2].y, ah[am][3].y, b0.x, b1.x);
                }
            }
        }
        __syncthreads();
    }

    // --- epilogue: scale columns by invdeg, store to g_Xs ---
    int cbase = blockIdx.x * BN + wn * 64;
    float2 sc[8];
    #pragma unroll
    for (int an = 0; an < 8; an++) {
        int gc = cbase + an * 8 + tq * 2;
        sc[an].x = g_invdeg[b * CC + gc];
        sc[an].y = g_invdeg[b * CC + gc + 1];
    }
    float* outp = g_Xs + (size_t)b * WW * CC;
    #pragma unroll
    for (int am = 0; am < 2; am++) {
        int grow = blockIdx.y * BM + wm * 32 + am * 16 + quad;
        #pragma unroll
        for (int an = 0; an < 8; an++) {
            int gc = cbase + an * 8 + tq * 2;
            float2 v0 = make_float2(acc[am][an][0] * sc[an].x, acc[am][an][1] * sc[an].y);
            float2 v1 = make_float2(acc[am][an][2] * sc[an].x, acc[am][an][3] * sc[an].y);
            *(float2*)(outp + (size_t)grow * CC + gc) = v0;
            *(float2*)(outp + (size_t)(grow + 8) * CC + gc) = v1;
        }
    }
}

// ---------- K3: temporal token = row mean over C ----------
__global__ void token_kernel() {
    int gwarp = (blockIdx.x * blockDim.x + threadIdx.x) >> 5;
    int lane = threadIdx.x & 31;
    if (gwarp >= BB * WW) return;
    const float4* row = (const float4*)(g_Xs + (size_t)gwarp * CC);
    float s = 0.f;
    #pragma unroll
    for (int q = 0; q < 4; q++) {
        float4 v = row[lane + 32 * q];
        s += v.x + v.y + v.z + v.w;
    }
    #pragma unroll
    for (int o = 16; o; o >>= 1) s += __shfl_xor_sync(0xffffffffu, s, o);
    if (lane == 0) g_tt[gwarp] = s * (1.0f / CC);
}

// ---------- K4: fused band-attention + epilogue ----------
#define TI 32
#define CJ 64
#define K2CAP 40
#define XR (TI + 2 * K2CAP)     // 112
#define NDTMAX (2 * K2CAP + 1)  // 81

__global__ __launch_bounds__(128)
void epilogue_kernel(const float* __restrict__ lt,
                     const float* __restrict__ wq, const float* __restrict__ bq,
                     const float* __restrict__ wk, const float* __restrict__ bk,
                     const float* __restrict__ wv, const float* __restrict__ bv,
                     const float* __restrict__ wmu, const float* __restrict__ bmu,
                     const float* __restrict__ wsig, const float* __restrict__ bsig,
                     const int* __restrict__ k1p, const int* __restrict__ k2p,
                     float* __restrict__ out) {
    __shared__ float sX[XR][CJ];
    __shared__ float sW[TI][NDTMAX];
    __shared__ float sTT[XR];
    __shared__ float sSac[TI];

    int b = blockIdx.z, i0 = blockIdx.y * TI, c0 = blockIdx.x * CJ;
    int k1 = k1p[0], k2 = k2p[0];
    float invt = 1.0f / (softplusf(lt[0]) + 1e-4f);
    float vwq = wq[0], vbq = bq[0], vwk = wk[0], vbk = bk[0];
    float vwv = wv[0], vbv = bv[0];
    float vwmu = wmu[0], vbmu = bmu[0], vws = wsig[0], vbs = bsig[0];
    int tid = threadIdx.x;
    float* muo = out;
    float* sgo = out + (size_t)NN;
    float* sco = out + 2 * (size_t)NN;

    if (k2 <= K2CAP) {
        int jlo = i0 - k2;
        int nrows = TI + 2 * k2;
        int ndt = 2 * k2 + 1;
        for (int idx = tid; idx < nrows * (CJ / 4); idx += 128) {
            int row = idx >> 4;
            int c4 = (idx & 15) * 4;
            int j = jlo + row;
            float4 v = make_float4(0.f, 0.f, 0.f, 0.f);
            if (j >= 0 && j < WW)
                v = *(const float4*)(g_Xs + (size_t)(b * WW + j) * CC + c0 + c4);
            *(float4*)&sX[row][c4] = v;
        }
        for (int idx = tid; idx < nrows; idx += 128) {
            int j = jlo + idx;
            sTT[idx] = (j >= 0 && j < WW) ? g_tt[b * WW + j] : 0.f;
        }
        __syncthreads();

        int lane = tid & 31, wid = tid >> 5;
        for (int r = wid; r < TI; r += 4) {
            int i = i0 + r;
            float qi = fmaf(vwq, sTT[r + k2], vbq);
            float m = -CUDART_INF_F;
            for (int p = lane; p < ndt; p += 32) {
                int dt = p - k2;
                int j = i + dt;
                bool valid = (abs(dt) >= k1) && (j >= 0) && (j < WW);
                float l = valid ? qi * fmaf(vwk, sTT[r + p], vbk) * invt : -CUDART_INF_F;
                sW[r][p] = l;
                m = fmaxf(m, l);
            }
            #pragma unroll
            for (int o = 16; o; o >>= 1) m = fmaxf(m, __shfl_xor_sync(0xffffffffu, m, o));
            if (m == -CUDART_INF_F) {
                for (int p = lane; p < ndt; p += 32) sW[r][p] = 0.f;
                __syncwarp();
                if (lane == 0) {
                    sW[r][k2] = 1.0f / (1.f + 1e-6f);
                    sSac[r] = 1.0f / (1.f + 1e-6f);
                }
            } else {
                float zs = 0.f;
                for (int p = lane; p < ndt; p += 32) {
                    float e = expf(sW[r][p] - m);
                    sW[r][p] = e;
                    zs += e;
                }
                #pragma unroll
                for (int o = 16; o; o >>= 1) zs += __shfl_xor_sync(0xffffffffu, zs, o);
                float invz = 1.0f / zs;
                float s2 = 0.f;
                for (int p = lane; p < ndt; p += 32) {
                    float en = sW[r][p] * invz;
                    sW[r][p] = en;
                    s2 += en;
                }
                #pragma unroll
                for (int o = 16; o; o >>= 1) s2 += __shfl_xor_sync(0xffffffffu, s2, o);
                float invd = 1.0f / (s2 + 1e-6f);
                for (int p = lane; p < ndt; p += 32) sW[r][p] *= invd;
                if (lane == 0) sSac[r] = s2 * invd;
            }
        }
        __syncthreads();

        int tx = tid & 15, ty = tid >> 4;
        int col = tx * 4;
        #pragma unroll
        for (int rr = 0; rr < 4; rr++) {
            int r = ty * 4 + rr;
            int i = i0 + r;
            float4 a = make_float4(0.f, 0.f, 0.f, 0.f);
            for (int p = 0; p < ndt; p++) {
                float w = sW[r][p];
                float4 x = *(const float4*)&sX[r + p][col];
                a.x = fmaf(w, x.x, a.x);
                a.y = fmaf(w, x.y, a.y);
                a.z = fmaf(w, x.z, a.z);
                a.w = fmaf(w, x.w, a.w);
            }
            float sac = sSac[r];
            float4 xo = *(const float4*)&sX[r + k2][col];
            float4 xf, mu, sg;
            xf.x = fmaf(vwv, a.x, vbv * sac) + xo.x;
            xf.y = fmaf(vwv, a.y, vbv * sac) + xo.y;
            xf.z = fmaf(vwv, a.z, vbv * sac) + xo.z;
            xf.w = fmaf(vwv, a.w, vbv * sac) + xo.w;
            mu.x = fminf(fmaxf(fmaf(vwmu, xf.x, vbmu), -20.f), 20.f);
            mu.y = fminf(fmaxf(fmaf(vwmu, xf.y, vbmu), -20.f), 20.f);
            mu.z = fminf(fmaxf(fmaf(vwmu, xf.z, vbmu), -20.f), 20.f);
            mu.w = fminf(fmaxf(fmaf(vwmu, xf.w, vbmu), -20.f), 20.f);
            sg.x = softplusf(fmaf(vws, xf.x, vbs)) + 0.1f;
            sg.y = softplusf(fmaf(vws, xf.y, vbs)) + 0.1f;
            sg.z = softplusf(fmaf(vws, xf.z, vbs)) + 0.1f;
            sg.w = softplusf(fmaf(vws, xf.w, vbs)) + 0.1f;
            size_t o = (size_t)(b * WW + i) * CC + c0 + col;
            *(float4*)(muo + o) = mu;
            *(float4*)(sgo + o) = sg;
            *(float4*)(sco + o) = make_float4(sac, sac, sac, sac);
        }
    } else {
        // correct slow fallback for k2 > K2CAP
        int tx = tid & 15, ty = tid >> 4;
        int col = c0 + tx * 4;
        for (int rr = 0; rr < 4; rr++) {
            int r = ty * 4 + rr;
            int i = i0 + r;
            float qi = fmaf(vwq, g_tt[b * WW + i], vbq);
            float m = -CUDART_INF_F;
            for (int dt = -k2; dt <= k2; dt++) {
                int j = i + dt;
                if (abs(dt) < k1 || j < 0 || j >= WW) continue;
                float l = qi * fmaf(vwk, g_tt[b * WW + j], vbk) * invt;
                m = fmaxf(m, l);
            }
            float4 a = make_float4(0.f, 0.f, 0.f, 0.f);
            float sac = 1.0f / (1.f + 1e-6f);
            if (m == -CUDART_INF_F) {
                float w = sac;
                float4 xi = *(const float4*)(g_Xs + (size_t)(b * WW + i) * CC + col);
                a.x = w * xi.x; a.y = w * xi.y; a.z = w * xi.z; a.w = w * xi.w;
            } else {
                float Z = 0.f;
                for (int dt = -k2; dt <= k2; dt++) {
                    int j = i + dt;
                    if (abs(dt) < k1 || j < 0 || j >= WW) continue;
                    float l = qi * fmaf(vwk, g_tt[b * WW + j], vbk) * invt;
                    float e = expf(l - m);
                    Z += e;
                    float4 x = *(const float4*)(g_Xs + (size_t)(b * WW + j) * CC + col);
                    a.x = fmaf(e, x.x, a.x);
                    a.y = fmaf(e, x.y, a.y);
                    a.z = fmaf(e, x.z, a.z);
                    a.w = fmaf(e, x.w, a.w);
                }
                float s = 1.0f / (Z * (1.f + 1e-6f));
                a.x *= s; a.y *= s; a.z *= s; a.w *= s;
            }
            float4 xo = *(const float4*)(g_Xs + (size_t)(b * WW + i) * CC + col);
            float4 xf, mu, sg;
            xf.x = fmaf(vwv, a.x, vbv * sac) + xo.x;
            xf.y = fmaf(vwv, a.y, vbv * sac) + xo.y;
            xf.z = fmaf(vwv, a.z, vbv * sac) + xo.z;
            xf.w = fmaf(vwv, a.w, vbv * sac) + xo.w;
            mu.x = fminf(fmaxf(fmaf(vwmu, xf.x, vbmu), -20.f), 20.f);
            mu.y = fminf(fmaxf(fmaf(vwmu, xf.y, vbmu), -20.f), 20.f);
            mu.z = fminf(fmaxf(fmaf(vwmu, xf.z, vbmu), -20.f), 20.f);
            mu.w = fminf(fmaxf(fmaf(vwmu, xf.w, vbmu), -20.f), 20.f);
            sg.x = softplusf(fmaf(vws, xf.x, vbs)) + 0.1f;
            sg.y = softplusf(fmaf(vws, xf.y, vbs)) + 0.1f;
            sg.z = softplusf(fmaf(vws, xf.z, vbs)) + 0.1f;
            sg.w = softplusf(fmaf(vws, xf.w, vbs)) + 0.1f;
            size_t o = (size_t)(b * WW + i) * CC + col;
            *(float4*)(muo + o) = mu;
            *(float4*)(sgo + o) = sg;
            *(float4*)(sco + o) = make_float4(sac, sac, sac, sac);
        }
    }
}

// ---------- launch ----------
extern "C" void kernel_launch(void* const* d_in, const int* in_sizes, int n_in,
                              void* d_out, int out_size) {
    const float* X    = (const float*)d_in[0];
    const float* adj  = (const float*)d_in[1];
    const float* lt   = (const float*)d_in[2];
    const float* wq   = (const float*)d_in[3];
    const float* bq   = (const float*)d_in[4];
    const float* wk   = (const float*)d_in[5];
    const float* bk   = (const float*)d_in[6];
    const float* wv   = (const float*)d_in[7];
    const float* bv   = (const float*)d_in[8];
    const float* wmu  = (const float*)d_in[9];
    const float* bmu  = (const float*)d_in[10];
    const float* wsig = (const float*)d_in[11];
    const float* bsig = (const float*)d_in[12];
    const int*   k1p  = (const int*)d_in[13];
    const int*   k2p  = (const int*)d_in[14];
    float* out = (float*)d_out;

    dim3 g1(8, BB);
    deg_partial_kernel<<<g1, 256>>>(adj);
    invdeg_kernel<<<(BB * CC + 255) / 256, 256>>>();
    dim3 g2(CC / BN, WW / BM, BB);
    gemm_kernel<<<g2, 256>>>(X, adj);
    token_kernel<<<(BB * WW) / 8, 256>>>();
    dim3 g5(CC / CJ, WW / TI, BB);
    epilogue_kernel<<<g5, 128>>>(lt, wq, bq, wk, bk, wv, bv, wmu, bmu, wsig, bsig,
                                 k1p, k2p, out);
}

// round 3
// speedup vs baseline: 2.5538x; 1.5420x over previous
#include <cuda_runtime.h>
#include <cuda_bf16.h>
#include <math_constants.h>
#include <cstdint>

#define BB 16
#define WW 2048
#define CC 512
#define NN (BB*WW*CC)

// ---------- scratch (no allocations allowed) ----------
__device__ float g_Xs[NN];           // X_spatial [B,W,C]  (64 MB)
__device__ float g_tt[BB*WW];        // temporal token mean [B,W]
__device__ float g_invdeg[BB*CC];    // 1/in_deg [B,C]
__device__ float g_degpart[BB*8*CC]; // partial column sums

__device__ __forceinline__ float softplusf(float x) {
    return fmaxf(x, 0.f) + log1pf(expf(-fabsf(x)));
}

// pack two consecutive values as (hi bf16x2, lo bf16x2)
__device__ __forceinline__ uint2 bf16x3_pack(float v0, float v1) {
    __nv_bfloat16 h0 = __float2bfloat16(v0);
    __nv_bfloat16 h1 = __float2bfloat16(v1);
    float r0 = v0 - __bfloat162float(h0);
    float r1 = v1 - __bfloat162float(h1);
    __nv_bfloat16 l0 = __float2bfloat16(r0);
    __nv_bfloat16 l1 = __float2bfloat16(r1);
    uint2 p;
    p.x = (uint32_t)__bfloat16_as_ushort(h0) | ((uint32_t)__bfloat16_as_ushort(h1) << 16);
    p.y = (uint32_t)__bfloat16_as_ushort(l0) | ((uint32_t)__bfloat16_as_ushort(l1) << 16);
    return p;
}

__device__ __forceinline__ void mma_bf16(float* c,
                                         uint32_t a0, uint32_t a1, uint32_t a2, uint32_t a3,
                                         uint32_t b0, uint32_t b1) {
    asm volatile(
        "mma.sync.aligned.m16n8k16.row.col.f32.bf16.bf16.f32 "
        "{%0,%1,%2,%3},{%4,%5,%6,%7},{%8,%9},{%0,%1,%2,%3};\n"
        : "+f"(c[0]), "+f"(c[1]), "+f"(c[2]), "+f"(c[3])
        : "r"(a0), "r"(a1), "r"(a2), "r"(a3), "r"(b0), "r"(b1));
}

// ---------- K1a: partial column sums of relu(adj) ----------
__global__ void deg_partial_kernel(const float* __restrict__ adj) {
    int b = blockIdx.y, chunk = blockIdx.x;
    int i0 = chunk * 64;
    const float* A = adj + (size_t)b * CC * CC;
    for (int j = threadIdx.x; j < CC; j += blockDim.x) {
        float s = 0.f;
        #pragma unroll 8
        for (int i = 0; i < 64; i++)
            s += fmaxf(A[(size_t)(i0 + i) * CC + j], 0.f);
        g_degpart[(b * 8 + chunk) * CC + j] = s;
    }
}

// ---------- K1b: reduce + invert ----------
__global__ void invdeg_kernel() {
    int idx = blockIdx.x * blockDim.x + threadIdx.x;
    if (idx >= BB * CC) return;
    int b = idx / CC, j = idx % CC;
    float s = 0.f;
    #pragma unroll
    for (int c = 0; c < 8; c++) s += g_degpart[(b * 8 + c) * CC + j];
    g_invdeg[idx] = 1.0f / fmaxf(s, 1e-4f);
}

// ---------- K2: 3xBF16 tensor-core SGEMM ----------
// Xs[b] = X[b] @ relu(adj[b]) * invdeg_col
#define BM 128
#define BN 128
#define BK 16
#define ASTRIDE 20    // uint2 stride (k-pairs), conflict-free fragment reads
#define BSTRIDE 132   // uint2 stride (cols), conflict-free fragment reads

__global__ __launch_bounds__(256, 2)
void gemm_kernel(const float* __restrict__ X, const float* __restrict__ adj) {
    __shared__ uint2 As[BM][ASTRIDE];       // [m][kpair] (hi,lo) bf16x2
    __shared__ uint2 Bs[BK / 2][BSTRIDE];   // [kpair][n] (hi,lo) bf16x2

    int b = blockIdx.z;
    const float* Ap = X + (size_t)b * WW * CC + (size_t)blockIdx.y * BM * CC;
    const float* Bp = adj + (size_t)b * CC * CC + blockIdx.x * BN;

    int tid = threadIdx.x;
    int lane = tid & 31, wid = tid >> 5;
    int quad = lane >> 2, tq = lane & 3;
    int wm = wid >> 1, wn = wid & 1;     // warp tile: rows [wm*32,+32), cols [wn*64,+64)

    // global load indices
    int a_row = tid >> 1;                // 0..127
    int a_k8  = (tid & 1) * 8;           // 0 or 8
    int b_kp  = tid >> 5;                // 0..7  (k-pair index)
    int b_n4  = (tid & 31) * 4;          // 0..124

    float acc[2][8][4];
    #pragma unroll
    for (int am = 0; am < 2; am++)
        #pragma unroll
        for (int an = 0; an < 8; an++)
            #pragma unroll
            for (int q = 0; q < 4; q++) acc[am][an][q] = 0.f;

    for (int k0 = 0; k0 < CC; k0 += BK) {
        // --- A tile: 2 float4 per thread -> 4 (hi,lo) k-pairs ---
        #pragma unroll
        for (int h = 0; h < 2; h++) {
            float4 v = *(const float4*)(Ap + (size_t)a_row * CC + k0 + a_k8 + h * 4);
            As[a_row][(a_k8 >> 1) + h * 2 + 0] = bf16x3_pack(v.x, v.y);
            As[a_row][(a_k8 >> 1) + h * 2 + 1] = bf16x3_pack(v.z, v.w);
        }
        // --- B tile (relu on load): pack k-pairs from two k rows ---
        {
            float4 v0 = *(const float4*)(Bp + (size_t)(k0 + 2 * b_kp) * CC + b_n4);
            float4 v1 = *(const float4*)(Bp + (size_t)(k0 + 2 * b_kp + 1) * CC + b_n4);
            v0.x = fmaxf(v0.x, 0.f); v0.y = fmaxf(v0.y, 0.f);
            v0.z = fmaxf(v0.z, 0.f); v0.w = fmaxf(v0.w, 0.f);
            v1.x = fmaxf(v1.x, 0.f); v1.y = fmaxf(v1.y, 0.f);
            v1.z = fmaxf(v1.z, 0.f); v1.w = fmaxf(v1.w, 0.f);
            Bs[b_kp][b_n4 + 0] = bf16x3_pack(v0.x, v1.x);
            Bs[b_kp][b_n4 + 1] = bf16x3_pack(v0.y, v1.y);
            Bs[b_kp][b_n4 + 2] = bf16x3_pack(v0.z, v1.z);
            Bs[b_kp][b_n4 + 3] = bf16x3_pack(v0.w, v1.w);
        }
        __syncthreads();

        // --- one k16 mma step per tile ---
        uint2 ah[2][4];
        #pragma unroll
        for (int am = 0; am < 2; am++) {
            int r0 = wm * 32 + am * 16 + quad;
            ah[am][0] = As[r0][tq];
            ah[am][1] = As[r0 + 8][tq];
            ah[am][2] = As[r0][tq + 4];
            ah[am][3] = As[r0 + 8][tq + 4];
        }
        #pragma unroll
        for (int an = 0; an < 8; an++) {
            int c0 = wn * 64 + an * 8 + quad;
            uint2 b0 = Bs[tq][c0];
            uint2 b1 = Bs[tq + 4][c0];
            #pragma unroll
            for (int am = 0; am < 2; am++) {
                float* c = acc[am][an];
                mma_bf16(c, ah[am][0].x, ah[am][1].x, ah[am][2].x, ah[am][3].x, b0.x, b1.x);
                mma_bf16(c, ah[am][0].x, ah[am][1].x, ah[am][2].x, ah[am][3].x, b0.y, b1.y);
                mma_bf16(c, ah[am][0].y, ah[am][1].y, ah[am][2].y, ah[am][3].y, b0.x, b1.x);
            }
        }
        __syncthreads();
    }

    // --- epilogue: scale columns by invdeg, store to g_Xs ---
    int cbase = blockIdx.x * BN + wn * 64;
    float2 sc[8];
    #pragma unroll
    for (int an = 0; an < 8; an++) {
        int gc = cbase + an * 8 + tq * 2;
        sc[an].x = g_invdeg[b * CC + gc];
        sc[an].y = g_invdeg[b * CC + gc + 1];
    }
    float* outp = g_Xs + (size_t)b * WW * CC;
    #pragma unroll
    for (int am = 0; am < 2; am++) {
        int grow = blockIdx.y * BM + wm * 32 + am * 16 + quad;
        #pragma unroll
        for (int an = 0; an < 8; an++) {
            int gc = cbase + an * 8 + tq * 2;
            float2 v0 = make_float2(acc[am][an][0] * sc[an].x, acc[am][an][1] * sc[an].y);
            float2 v1 = make_float2(acc[am][an][2] * sc[an].x, acc[am][an][3] * sc[an].y);
            *(float2*)(outp + (size_t)grow * CC + gc) = v0;
            *(float2*)(outp + (size_t)(grow + 8) * CC + gc) = v1;
        }
    }
}

// ---------- K3: temporal token = row mean over C ----------
__global__ void token_kernel() {
    int gwarp = (blockIdx.x * blockDim.x + threadIdx.x) >> 5;
    int lane = threadIdx.x & 31;
    if (gwarp >= BB * WW) return;
    const float4* row = (const float4*)(g_Xs + (size_t)gwarp * CC);
    float s = 0.f;
    #pragma unroll
    for (int q = 0; q < 4; q++) {
        float4 v = row[lane + 32 * q];
        s += v.x + v.y + v.z + v.w;
    }
    #pragma unroll
    for (int o = 16; o; o >>= 1) s += __shfl_xor_sync(0xffffffffu, s, o);
    if (lane == 0) g_tt[gwarp] = s * (1.0f / CC);
}

// ---------- K4: fused band-attention + epilogue ----------
#define TI 32
#define CJ 64
#define K2CAP 40
#define XR (TI + 2 * K2CAP)     // 112
#define NDTMAX (2 * K2CAP + 1)  // 81

__global__ __launch_bounds__(128)
void epilogue_kernel(const float* __restrict__ lt,
                     const float* __restrict__ wq, const float* __restrict__ bq,
                     const float* __restrict__ wk, const float* __restrict__ bk,
                     const float* __restrict__ wv, const float* __restrict__ bv,
                     const float* __restrict__ wmu, const float* __restrict__ bmu,
                     const float* __restrict__ wsig, const float* __restrict__ bsig,
                     const int* __restrict__ k1p, const int* __restrict__ k2p,
                     float* __restrict__ out) {
    __shared__ float sX[XR][CJ];
    __shared__ float sW[TI][NDTMAX];
    __shared__ float sTT[XR];
    __shared__ float sSac[TI];

    int b = blockIdx.z, i0 = blockIdx.y * TI, c0 = blockIdx.x * CJ;
    int k1 = k1p[0], k2 = k2p[0];
    float invt = 1.0f / (softplusf(lt[0]) + 1e-4f);
    float vwq = wq[0], vbq = bq[0], vwk = wk[0], vbk = bk[0];
    float vwv = wv[0], vbv = bv[0];
    float vwmu = wmu[0], vbmu = bmu[0], vws = wsig[0], vbs = bsig[0];
    int tid = threadIdx.x;
    float* muo = out;
    float* sgo = out + (size_t)NN;
    float* sco = out + 2 * (size_t)NN;

    if (k2 <= K2CAP) {
        int jlo = i0 - k2;
        int nrows = TI + 2 * k2;
        int ndt = 2 * k2 + 1;
        for (int idx = tid; idx < nrows * (CJ / 4); idx += 128) {
            int row = idx >> 4;
            int c4 = (idx & 15) * 4;
            int j = jlo + row;
            float4 v = make_float4(0.f, 0.f, 0.f, 0.f);
            if (j >= 0 && j < WW)
                v = *(const float4*)(g_Xs + (size_t)(b * WW + j) * CC + c0 + c4);
            *(float4*)&sX[row][c4] = v;
        }
        for (int idx = tid; idx < nrows; idx += 128) {
            int j = jlo + idx;
            sTT[idx] = (j >= 0 && j < WW) ? g_tt[b * WW + j] : 0.f;
        }
        __syncthreads();

        int lane = tid & 31, wid = tid >> 5;
        for (int r = wid; r < TI; r += 4) {
            int i = i0 + r;
            float qi = fmaf(vwq, sTT[r + k2], vbq);
            float m = -CUDART_INF_F;
            for (int p = lane; p < ndt; p += 32) {
                int dt = p - k2;
                int j = i + dt;
                bool valid = (abs(dt) >= k1) && (j >= 0) && (j < WW);
                float l = valid ? qi * fmaf(vwk, sTT[r + p], vbk) * invt : -CUDART_INF_F;
                sW[r][p] = l;
                m = fmaxf(m, l);
            }
            #pragma unroll
            for (int o = 16; o; o >>= 1) m = fmaxf(m, __shfl_xor_sync(0xffffffffu, m, o));
            if (m == -CUDART_INF_F) {
                for (int p = lane; p < ndt; p += 32) sW[r][p] = 0.f;
                __syncwarp();
                if (lane == 0) {
                    sW[r][k2] = 1.0f / (1.f + 1e-6f);
                    sSac[r] = 1.0f / (1.f + 1e-6f);
                }
            } else {
                float zs = 0.f;
                for (int p = lane; p < ndt; p += 32) {
                    float e = expf(sW[r][p] - m);
                    sW[r][p] = e;
                    zs += e;
                }
                #pragma unroll
                for (int o = 16; o; o >>= 1) zs += __shfl_xor_sync(0xffffffffu, zs, o);
                float invz = 1.0f / zs;
                float s2 = 0.f;
                for (int p = lane; p < ndt; p += 32) {
                    float en = sW[r][p] * invz;
                    sW[r][p] = en;
                    s2 += en;
                }
                #pragma unroll
                for (int o = 16; o; o >>= 1) s2 += __shfl_xor_sync(0xffffffffu, s2, o);
                float invd = 1.0f / (s2 + 1e-6f);
                for (int p = lane; p < ndt; p += 32) sW[r][p] *= invd;
                if (lane == 0) sSac[r] = s2 * invd;
            }
        }
        __syncthreads();

        // banded weighted sum restricted to the valid band (+ center term)
        int tx = tid & 15, ty = tid >> 4;
        int col = tx * 4;
        int pEnd1 = k2 - k1;                        // dt in [-k2,-k1]
        int pStart2 = k2 + (k1 > 0 ? k1 : 1);       // dt in [max(k1,1), k2]
        #pragma unroll
        for (int rr = 0; rr < 4; rr++) {
            int r = ty * 4 + rr;
            int i = i0 + r;
            float4 a = make_float4(0.f, 0.f, 0.f, 0.f);
            for (int p = 0; p <= pEnd1; p++) {
                float w = sW[r][p];
                float4 x = *(const float4*)&sX[r + p][col];
                a.x = fmaf(w, x.x, a.x);
                a.y = fmaf(w, x.y, a.y);
                a.z = fmaf(w, x.z, a.z);
                a.w = fmaf(w, x.w, a.w);
            }
            if (k1 > 0) {  // center (identity fallback weight lives here)
                float w = sW[r][k2];
                float4 x = *(const float4*)&sX[r + k2][col];
                a.x = fmaf(w, x.x, a.x);
                a.y = fmaf(w, x.y, a.y);
                a.z = fmaf(w, x.z, a.z);
                a.w = fmaf(w, x.w, a.w);
            }
            for (int p = pStart2; p <= 2 * k2; p++) {
                float w = sW[r][p];
                float4 x = *(const float4*)&sX[r + p][col];
                a.x = fmaf(w, x.x, a.x);
                a.y = fmaf(w, x.y, a.y);
                a.z = fmaf(w, x.z, a.z);
                a.w = fmaf(w, x.w, a.w);
            }
            float sac = sSac[r];
            float4 xo = *(const float4*)&sX[r + k2][col];
            float4 xf, mu, sg;
            xf.x = fmaf(vwv, a.x, vbv * sac) + xo.x;
            xf.y = fmaf(vwv, a.y, vbv * sac) + xo.y;
            xf.z = fmaf(vwv, a.z, vbv * sac) + xo.z;
            xf.w = fmaf(vwv, a.w, vbv * sac) + xo.w;
            mu.x = fminf(fmaxf(fmaf(vwmu, xf.x, vbmu), -20.f), 20.f);
            mu.y = fminf(fmaxf(fmaf(vwmu, xf.y, vbmu), -20.f), 20.f);
            mu.z = fminf(fmaxf(fmaf(vwmu, xf.z, vbmu), -20.f), 20.f);
            mu.w = fminf(fmaxf(fmaf(vwmu, xf.w, vbmu), -20.f), 20.f);
            sg.x = softplusf(fmaf(vws, xf.x, vbs)) + 0.1f;
            sg.y = softplusf(fmaf(vws, xf.y, vbs)) + 0.1f;
            sg.z = softplusf(fmaf(vws, xf.z, vbs)) + 0.1f;
            sg.w = softplusf(fmaf(vws, xf.w, vbs)) + 0.1f;
            size_t o = (size_t)(b * WW + i) * CC + c0 + col;
            *(float4*)(muo + o) = mu;
            *(float4*)(sgo + o) = sg;
            *(float4*)(sco + o) = make_float4(sac, sac, sac, sac);
        }
    } else {
        // correct slow fallback for k2 > K2CAP
        int tx = tid & 15, ty = tid >> 4;
        int col = c0 + tx * 4;
        for (int rr = 0; rr < 4; rr++) {
            int r = ty * 4 + rr;
            int i = i0 + r;
            float qi = fmaf(vwq, g_tt[b * WW + i], vbq);
            float m = -CUDART_INF_F;
            for (int dt = -k2; dt <= k2; dt++) {
                int j = i + dt;
                if (abs(dt) < k1 || j < 0 || j >= WW) continue;
                float l = qi * fmaf(vwk, g_tt[b * WW + j], vbk) * invt;
                m = fmaxf(m, l);
            }
            float4 a = make_float4(0.f, 0.f, 0.f, 0.f);
            float sac = 1.0f / (1.f + 1e-6f);
            if (m == -CUDART_INF_F) {
                float w = sac;
                float4 xi = *(const float4*)(g_Xs + (size_t)(b * WW + i) * CC + col);
                a.x = w * xi.x; a.y = w * xi.y; a.z = w * xi.z; a.w = w * xi.w;
            } else {
                float Z = 0.f;
                for (int dt = -k2; dt <= k2; dt++) {
                    int j = i + dt;
                    if (abs(dt) < k1 || j < 0 || j >= WW) continue;
                    float l = qi * fmaf(vwk, g_tt[b * WW + j], vbk) * invt;
                    float e = expf(l - m);
                    Z += e;
                    float4 x = *(const float4*)(g_Xs + (size_t)(b * WW + j) * CC + col);
                    a.x = fmaf(e, x.x, a.x);
                    a.y = fmaf(e, x.y, a.y);
                    a.z = fmaf(e, x.z, a.z);
                    a.w = fmaf(e, x.w, a.w);
                }
                float s = 1.0f / (Z * (1.f + 1e-6f));
                a.x *= s; a.y *= s; a.z *= s; a.w *= s;
            }
            float4 xo = *(const float4*)(g_Xs + (size_t)(b * WW + i) * CC + col);
            float4 xf, mu, sg;
            xf.x = fmaf(vwv, a.x, vbv * sac) + xo.x;
            xf.y = fmaf(vwv, a.y, vbv * sac) + xo.y;
            xf.z = fmaf(vwv, a.z, vbv * sac) + xo.z;
            xf.w = fmaf(vwv, a.w, vbv * sac) + xo.w;
            mu.x = fminf(fmaxf(fmaf(vwmu, xf.x, vbmu), -20.f), 20.f);
            mu.y = fminf(fmaxf(fmaf(vwmu, xf.y, vbmu), -20.f), 20.f);
            mu.z = fminf(fmaxf(fmaf(vwmu, xf.z, vbmu), -20.f), 20.f);
            mu.w = fminf(fmaxf(fmaf(vwmu, xf.w, vbmu), -20.f), 20.f);
            sg.x = softplusf(fmaf(vws, xf.x, vbs)) + 0.1f;
            sg.y = softplusf(fmaf(vws, xf.y, vbs)) + 0.1f;
            sg.z = softplusf(fmaf(vws, xf.z, vbs)) + 0.1f;
            sg.w = softplusf(fmaf(vws, xf.w, vbs)) + 0.1f;
            size_t o = (size_t)(b * WW + i) * CC + col;
            *(float4*)(muo + o) = mu;
            *(float4*)(sgo + o) = sg;
            *(float4*)(sco + o) = make_float4(sac, sac, sac, sac);
        }
    }
}

// ---------- launch ----------
extern "C" void kernel_launch(void* const* d_in, const int* in_sizes, int n_in,
                              void* d_out, int out_size) {
    const float* X    = (const float*)d_in[0];
    const float* adj  = (const float*)d_in[1];
    const float* lt   = (const float*)d_in[2];
    const float* wq   = (const float*)d_in[3];
    const float* bq   = (const float*)d_in[4];
    const float* wk   = (const float*)d_in[5];
    const float* bk   = (const float*)d_in[6];
    const float* wv   = (const float*)d_in[7];
    const float* bv   = (const float*)d_in[8];
    const float* wmu  = (const float*)d_in[9];
    const float* bmu  = (const float*)d_in[10];
    const float* wsig = (const float*)d_in[11];
    const float* bsig = (const float*)d_in[12];
    const int*   k1p  = (const int*)d_in[13];
    const int*   k2p  = (const int*)d_in[14];
    float* out = (float*)d_out;

    dim3 g1(8, BB);
    deg_partial_kernel<<<g1, 256>>>(adj);
    invdeg_kernel<<<(BB * CC + 255) / 256, 256>>>();
    dim3 g2(CC / BN, WW / BM, BB);
    gemm_kernel<<<g2, 256>>>(X, adj);
    token_kernel<<<(BB * WW) / 8, 256>>>();
    dim3 g5(CC / CJ, WW / TI, BB);
    epilogue_kernel<<<g5, 128>>>(lt, wq, bq, wk, bk, wv, bv, wmu, bmu, wsig, bsig,
                                 k1p, k2p, out);
}